// round 12
// baseline (speedup 1.0000x reference)
#include <cuda_runtime.h>
#include <cuda_bf16.h>
#include <math.h>
#include <stdint.h>

#define NSPK 512
#define UUT  32
#define DIM  512
#define MROW 16384          // 512*32
#define EPSF 1e-8f

// ------------------------- device scratch (no allocs) ------------------------
__device__ __nv_bfloat16 g_A[(size_t)MROW * DIM];   // 16 MB bf16(e)
__device__ __nv_bfloat16 g_B[(size_t)DIM * NSPK];   // 512x512 normalized centroids [k][n]
__device__ float g_invA[MROW];
__device__ float g_se[MROW];                        // sum of exp per row
__device__ float g_vd[MROW];                        // diag value per row
__device__ unsigned int g_cnt[MROW / 128];          // per-M-block completion counters

// ------------------------------- PTX helpers ---------------------------------
__device__ __forceinline__ uint32_t smem_u32(const void* p) {
    uint32_t a;
    asm("{ .reg .u64 t; cvta.to.shared.u64 t, %1; cvt.u32.u64 %0, t; }"
        : "=r"(a) : "l"(p));
    return a;
}

#define CP_ASYNC16(dst, src) \
    asm volatile("cp.async.cg.shared.global [%0], [%1], 16;" :: "r"(dst), "l"(src))
#define CP_COMMIT() asm volatile("cp.async.commit_group;" ::: "memory")
#define CP_WAIT2()  asm volatile("cp.async.wait_group 2;" ::: "memory")
#define CP_WAIT1()  asm volatile("cp.async.wait_group 1;" ::: "memory")
#define CP_WAIT0()  asm volatile("cp.async.wait_group 0;" ::: "memory")

#define LDSM_X4(r, addr) \
    asm volatile("ldmatrix.sync.aligned.m8n8.x4.shared.b16 {%0,%1,%2,%3}, [%4];" \
        : "=r"((r)[0]), "=r"((r)[1]), "=r"((r)[2]), "=r"((r)[3]) : "r"(addr))
#define LDSM_X4T(r, addr) \
    asm volatile("ldmatrix.sync.aligned.m8n8.x4.trans.shared.b16 {%0,%1,%2,%3}, [%4];" \
        : "=r"((r)[0]), "=r"((r)[1]), "=r"((r)[2]), "=r"((r)[3]) : "r"(addr))

#define MMA16816(c, a, b0, b1) \
    asm volatile("mma.sync.aligned.m16n8k16.row.col.f32.bf16.bf16.f32 " \
        "{%0,%1,%2,%3}, {%4,%5,%6,%7}, {%8,%9}, {%0,%1,%2,%3};" \
        : "+f"((c)[0]), "+f"((c)[1]), "+f"((c)[2]), "+f"((c)[3]) \
        : "r"((a)[0]), "r"((a)[1]), "r"((a)[2]), "r"((a)[3]), "r"(b0), "r"(b1))

// A tile: 128 rows x 128B (64 bf16/row), SW128 swizzle, g = granule 0..7
__device__ __forceinline__ uint32_t aoff2(int row, int g) {
    return (uint32_t)(row * 128 + ((g ^ (row & 7)) << 4));
}
// B tile: 64 rows (k) x 256B (128 bf16), 16 granules/row, XOR with k&7
__device__ __forceinline__ uint32_t boff(int k, int g) {
    return (uint32_t)(k * 256 + ((g ^ (k & 7)) << 4));
}

__device__ __forceinline__ uint32_t pack2(float x, float y) {
    __nv_bfloat162 p;
    p.x = __float2bfloat16(x);
    p.y = __float2bfloat16(y);
    return *reinterpret_cast<uint32_t*>(&p);
}

// -----------------------------------------------------------------------------
// Kernel 1a (conv): pure stream. warp = row; 4x LDG.128 -> 4x STG.64 + norm.
// Also zeroes g_se, g_cnt and d_out (graph-replay deterministic).
// -----------------------------------------------------------------------------
__global__ __launch_bounds__(256) void conv_kernel(const float* __restrict__ e,
                                                   float* __restrict__ out) {
    int w = threadIdx.x >> 5, lane = threadIdx.x & 31;
    int r = blockIdx.x * 8 + w;
    if (blockIdx.x == 0 && threadIdx.x == 0) out[0] = 0.f;
    if (blockIdx.x < (MROW / 128) / 256 + 1) {
        int idx = blockIdx.x * 256 + threadIdx.x;
        if (idx < MROW / 128) g_cnt[idx] = 0u;
    }
    if (lane == 1) g_se[r] = 0.f;

    const float4* src = (const float4*)(e + (size_t)r * DIM);
    float4 v[4];
#pragma unroll
    for (int i = 0; i < 4; ++i) v[i] = src[i * 32 + lane];

    uint2* dst = (uint2*)(g_A + (size_t)r * DIM);
    float ss = 0.f;
#pragma unroll
    for (int i = 0; i < 4; ++i) {
        float4 q = v[i];
        ss += q.x * q.x + q.y * q.y + q.z * q.z + q.w * q.w;
        dst[i * 32 + lane] = make_uint2(pack2(q.x, q.y), pack2(q.z, q.w));
    }
#pragma unroll
    for (int s = 16; s > 0; s >>= 1) ss += __shfl_xor_sync(0xffffffffu, ss, s);
    if (lane == 0) g_invA[r] = 1.0f / fmaxf(sqrtf(ss), EPSF);
}

// -----------------------------------------------------------------------------
// Kernel 1b (centroid): block = speaker j; fp32 sums (L2-warm e) -> g_B [k][n].
// -----------------------------------------------------------------------------
__global__ __launch_bounds__(256) void centroid_kernel(const float* __restrict__ e) {
    int j = blockIdx.x, tid = threadIdx.x;
    const float* base = e + (size_t)j * UUT * DIM;
    float s0 = 0.f, s1 = 0.f;
#pragma unroll 4
    for (int u = 0; u < UUT; ++u) {
        s0 += base[u * DIM + tid];
        s1 += base[u * DIM + tid + 256];
    }
    __shared__ float red[256];
    red[tid] = s0 * s0 + s1 * s1;
    __syncthreads();
    for (int s = 128; s > 0; s >>= 1) {
        if (tid < s) red[tid] += red[tid + s];
        __syncthreads();
    }
    float inv = 1.0f / fmaxf(sqrtf(red[0]), 32.f * EPSF);
    g_B[(size_t)tid * NSPK + j]         = __float2bfloat16(s0 * inv);
    g_B[(size_t)(tid + 256) * NSPK + j] = __float2bfloat16(s1 * inv);
}

// -----------------------------------------------------------------------------
// Kernel 2: bf16 mma.sync GEMM, BM=BN=128, BK=64, 3-stage cp.async,
// fused softmax-partial epilogue + LAST-CTA final reduction (no final kernel).
// smem: 3 stages x 32KB = 96KB + 512B se_sm.
// -----------------------------------------------------------------------------
#define NKT 8            // DIM / 64
#define GEMM_SMEM (98304 + 512)

__global__ __launch_bounds__(256) void gemm_fused_kernel(const float* __restrict__ wp,
                                                         const float* __restrict__ bp,
                                                         float* __restrict__ out) {
    extern __shared__ __align__(1024) char smem[];
    float* se_sm = (float*)(smem + 98304);

    int tid = threadIdx.x;
    int lane = tid & 31, wid = tid >> 5;
    int warp_m = wid & 1, warp_n = wid >> 1;
    int mBase = blockIdx.y * 128, nBase = blockIdx.x * 128;

    uint32_t sbase = smem_u32(smem);

    int arow = tid >> 3, ag = tid & 7;
    int brow = tid >> 4, bg = tid & 15;
    const __nv_bfloat16* aptr = g_A + (size_t)(mBase + arow) * DIM + ag * 8;
    const __nv_bfloat16* bptr = g_B + (size_t)brow * NSPK + nBase + bg * 8;

    float c[4][4][4];
#pragma unroll
    for (int i = 0; i < 4; ++i)
#pragma unroll
        for (int j = 0; j < 4; ++j)
#pragma unroll
            for (int q = 0; q < 4; ++q) c[i][j][q] = 0.f;

#define LOAD_STAGE(s, kt) do {                                                  \
        int k0 = (kt) * 64;                                                     \
        uint32_t sA_ = sbase + (s) * 32768;                                     \
        uint32_t sB_ = sA_ + 16384;                                             \
        CP_ASYNC16(sA_ + aoff2(arow,      ag), aptr + k0);                      \
        CP_ASYNC16(sA_ + aoff2(arow + 32, ag), aptr + k0 + (size_t)32 * DIM);   \
        CP_ASYNC16(sA_ + aoff2(arow + 64, ag), aptr + k0 + (size_t)64 * DIM);   \
        CP_ASYNC16(sA_ + aoff2(arow + 96, ag), aptr + k0 + (size_t)96 * DIM);   \
        CP_ASYNC16(sB_ + boff(brow,      bg), bptr + (size_t)(k0     ) * NSPK); \
        CP_ASYNC16(sB_ + boff(brow + 16, bg), bptr + (size_t)(k0 + 16) * NSPK); \
        CP_ASYNC16(sB_ + boff(brow + 32, bg), bptr + (size_t)(k0 + 32) * NSPK); \
        CP_ASYNC16(sB_ + boff(brow + 48, bg), bptr + (size_t)(k0 + 48) * NSPK); \
        CP_COMMIT();                                                            \
    } while (0)

    LOAD_STAGE(0, 0);
    LOAD_STAGE(1, 1);
    LOAD_STAGE(2, 2);

    int lrow = lane & 15, lsel = lane >> 4;

    for (int kt = 0; kt < NKT; ++kt) {
        if (kt < NKT - 2)       CP_WAIT2();
        else if (kt == NKT - 2) CP_WAIT1();
        else                    CP_WAIT0();
        __syncthreads();

        int s = kt % 3;
        uint32_t sA = sbase + s * 32768;
        uint32_t sB = sA + 16384;

#pragma unroll
        for (int kh = 0; kh < 4; ++kh) {
            uint32_t a[4][4], b[2][4];
#pragma unroll
            for (int mt = 0; mt < 4; ++mt) {
                int row = warp_m * 64 + mt * 16 + lrow;
                LDSM_X4(a[mt], sA + aoff2(row, kh * 2 + lsel));
            }
#pragma unroll
            for (int nt = 0; nt < 2; ++nt) {
                int k = kh * 16 + lrow;
                LDSM_X4T(b[nt], sB + boff(k, warp_n * 4 + nt * 2 + lsel));
            }
#pragma unroll
            for (int mt = 0; mt < 4; ++mt)
#pragma unroll
                for (int n8 = 0; n8 < 4; ++n8) {
                    uint32_t b0 = b[n8 >> 1][(n8 & 1) * 2];
                    uint32_t b1 = b[n8 >> 1][(n8 & 1) * 2 + 1];
                    MMA16816(c[mt][n8], a[mt], b0, b1);
                }
        }
        __syncthreads();
        if (kt + 3 < NKT) LOAD_STAGE((kt + 3) % 3, kt + 3);
    }
#undef LOAD_STAGE

    // ---------------- fused epilogue: partial sum-exp + diag -----------------
    if (tid < 128) se_sm[tid] = 0.f;
    __syncthreads();

    float wv = *wp, bv = *bp;
#pragma unroll
    for (int mt = 0; mt < 4; ++mt) {
#pragma unroll
        for (int sr = 0; sr < 2; ++sr) {
            int row_l = warp_m * 64 + mt * 16 + (lane >> 2) + sr * 8;
            int row_g = mBase + row_l;
            float sc = wv * g_invA[row_g];
            int jdiag = row_g >> 5;
            float part = 0.f;
#pragma unroll
            for (int n8 = 0; n8 < 4; ++n8) {
#pragma unroll
                for (int cc = 0; cc < 2; ++cc) {
                    int col_g = nBase + warp_n * 32 + n8 * 8 + (lane & 3) * 2 + cc;
                    float v = fmaf(c[mt][n8][sr * 2 + cc], sc, bv);
                    part += __expf(v);
                    if (col_g == jdiag) g_vd[row_g] = v;
                }
            }
            part += __shfl_xor_sync(0xffffffffu, part, 1);
            part += __shfl_xor_sync(0xffffffffu, part, 2);
            if ((lane & 3) == 0) atomicAdd(&se_sm[row_l], part);
        }
    }
    __syncthreads();
    if (tid < 128) atomicAdd(&g_se[mBase + tid], se_sm[tid]);

    // ------------- last-CTA-per-M-block final reduction (release/acquire) ----
    __threadfence();
    __syncthreads();
    __shared__ unsigned int s_old;
    if (tid == 0) s_old = atomicAdd(&g_cnt[blockIdx.y], 1u);
    __syncthreads();
    if (s_old == 3u) {   // all 4 column-CTAs for this M block are done
        if (tid < 128) {
            int row_g = mBase + tid;
            float v = __logf(__ldcg(&g_se[row_g])) - __ldcg(&g_vd[row_g]);
#pragma unroll
            for (int s = 16; s > 0; s >>= 1)
                v += __shfl_xor_sync(0xffffffffu, v, s);
            if (lane == 0) atomicAdd(out, v * (1.0f / (float)MROW));
        }
    }
}

// -----------------------------------------------------------------------------
extern "C" void kernel_launch(void* const* d_in, const int* in_sizes, int n_in,
                              void* d_out, int out_size) {
    const float* e = (const float*)d_in[0];  // (512, 32, 512) fp32
    const float* w = (const float*)d_in[1];
    const float* b = (const float*)d_in[2];
    float* out = (float*)d_out;

    cudaFuncSetAttribute(gemm_fused_kernel,
                         cudaFuncAttributeMaxDynamicSharedMemorySize, GEMM_SMEM);

    conv_kernel<<<MROW / 8, 256>>>(e, out);
    centroid_kernel<<<NSPK, 256>>>(e);
    gemm_fused_kernel<<<dim3(NSPK / 128, MROW / 128), 256, GEMM_SMEM>>>(w, b, out);
}

// round 14
// speedup vs baseline: 1.0461x; 1.0461x over previous
#include <cuda_runtime.h>
#include <cuda_bf16.h>
#include <math.h>
#include <stdint.h>

#define NSPK 512
#define UUT  32
#define DIM  512
#define MROW 16384          // 512*32
#define EPSF 1e-8f

// ------------------------- device scratch (no allocs) ------------------------
__device__ __nv_bfloat16 g_A[(size_t)MROW * DIM];   // 16 MB bf16(e)
__device__ __nv_bfloat16 g_B[(size_t)DIM * NSPK];   // 512x512 normalized centroids [k][n]
__device__ float g_invA[MROW];
__device__ float g_se[MROW];                        // sum of exp per row
__device__ float g_vd[MROW];                        // diag value per row

// ------------------------------- PTX helpers ---------------------------------
__device__ __forceinline__ uint32_t smem_u32(const void* p) {
    uint32_t a;
    asm("{ .reg .u64 t; cvta.to.shared.u64 t, %1; cvt.u32.u64 %0, t; }"
        : "=r"(a) : "l"(p));
    return a;
}

#define CP_ASYNC16(dst, src) \
    asm volatile("cp.async.cg.shared.global [%0], [%1], 16;" :: "r"(dst), "l"(src))
#define CP_COMMIT() asm volatile("cp.async.commit_group;" ::: "memory")
#define CP_WAIT2()  asm volatile("cp.async.wait_group 2;" ::: "memory")
#define CP_WAIT1()  asm volatile("cp.async.wait_group 1;" ::: "memory")
#define CP_WAIT0()  asm volatile("cp.async.wait_group 0;" ::: "memory")

#define LDSM_X4(r, addr) \
    asm volatile("ldmatrix.sync.aligned.m8n8.x4.shared.b16 {%0,%1,%2,%3}, [%4];" \
        : "=r"((r)[0]), "=r"((r)[1]), "=r"((r)[2]), "=r"((r)[3]) : "r"(addr))
#define LDSM_X4T(r, addr) \
    asm volatile("ldmatrix.sync.aligned.m8n8.x4.trans.shared.b16 {%0,%1,%2,%3}, [%4];" \
        : "=r"((r)[0]), "=r"((r)[1]), "=r"((r)[2]), "=r"((r)[3]) : "r"(addr))

#define MMA16816(c, a, b0, b1) \
    asm volatile("mma.sync.aligned.m16n8k16.row.col.f32.bf16.bf16.f32 " \
        "{%0,%1,%2,%3}, {%4,%5,%6,%7}, {%8,%9}, {%0,%1,%2,%3};" \
        : "+f"((c)[0]), "+f"((c)[1]), "+f"((c)[2]), "+f"((c)[3]) \
        : "r"((a)[0]), "r"((a)[1]), "r"((a)[2]), "r"((a)[3]), "r"(b0), "r"(b1))

// A tile: 128 rows x 128B (64 bf16/row), SW128 swizzle, g = granule 0..7
__device__ __forceinline__ uint32_t aoff2(int row, int g) {
    return (uint32_t)(row * 128 + ((g ^ (row & 7)) << 4));
}
// B tile: 64 rows (k) x 256B (128 bf16), 16 granules/row, XOR with k&7
__device__ __forceinline__ uint32_t boff(int k, int g) {
    return (uint32_t)(k * 256 + ((g ^ (k & 7)) << 4));
}

__device__ __forceinline__ uint32_t pack2(float x, float y) {
    __nv_bfloat162 p;
    p.x = __float2bfloat16(x);
    p.y = __float2bfloat16(y);
    return *reinterpret_cast<uint32_t*>(&p);
}

// -----------------------------------------------------------------------------
// Kernel 1a (conv): streaming convert. warp = 4 rows; ALL 16 LDG.128 batched
// up front (MLP 16/thread). No smem, no barriers. Zeroes g_se and d_out.
// -----------------------------------------------------------------------------
__global__ __launch_bounds__(256) void conv_kernel(const float* __restrict__ e,
                                                   float* __restrict__ out) {
    int w = threadIdx.x >> 5, lane = threadIdx.x & 31;
    int r0 = blockIdx.x * 32 + w * 4;
    if (blockIdx.x == 0 && threadIdx.x == 0) out[0] = 0.f;
    if (lane < 4) g_se[r0 + lane] = 0.f;

    // batch all 16 independent 16B loads
    float4 v[4][4];
#pragma unroll
    for (int uu = 0; uu < 4; ++uu) {
        const float4* src = (const float4*)(e + (size_t)(r0 + uu) * DIM);
#pragma unroll
        for (int i = 0; i < 4; ++i) v[uu][i] = src[i * 32 + lane];
    }

    float ss[4];
#pragma unroll
    for (int uu = 0; uu < 4; ++uu) {
        uint2* dst = (uint2*)(g_A + (size_t)(r0 + uu) * DIM);
        float s = 0.f;
#pragma unroll
        for (int i = 0; i < 4; ++i) {
            float4 q = v[uu][i];
            s += q.x * q.x + q.y * q.y + q.z * q.z + q.w * q.w;
            dst[i * 32 + lane] = make_uint2(pack2(q.x, q.y), pack2(q.z, q.w));
        }
        ss[uu] = s;
    }
    // 4 independent reduction chains interleave
#pragma unroll
    for (int s = 16; s > 0; s >>= 1) {
#pragma unroll
        for (int uu = 0; uu < 4; ++uu)
            ss[uu] += __shfl_xor_sync(0xffffffffu, ss[uu], s);
    }
    if (lane < 4) g_invA[r0 + lane] = 1.0f / fmaxf(sqrtf(ss[lane]), EPSF);
}

// -----------------------------------------------------------------------------
// Kernel 1b (centroid): block = speaker j; fp32 sums (L2-warm e) -> g_B [k][n].
// -----------------------------------------------------------------------------
__global__ __launch_bounds__(256) void centroid_kernel(const float* __restrict__ e) {
    int j = blockIdx.x, tid = threadIdx.x;
    const float* base = e + (size_t)j * UUT * DIM;
    float s0 = 0.f, s1 = 0.f;
#pragma unroll 4
    for (int u = 0; u < UUT; ++u) {
        s0 += base[u * DIM + tid];
        s1 += base[u * DIM + tid + 256];
    }
    __shared__ float red[256];
    red[tid] = s0 * s0 + s1 * s1;
    __syncthreads();
    for (int s = 128; s > 0; s >>= 1) {
        if (tid < s) red[tid] += red[tid + s];
        __syncthreads();
    }
    float inv = 1.0f / fmaxf(sqrtf(red[0]), 32.f * EPSF);
    g_B[(size_t)tid * NSPK + j]         = __float2bfloat16(s0 * inv);
    g_B[(size_t)(tid + 256) * NSPK + j] = __float2bfloat16(s1 * inv);
}

// -----------------------------------------------------------------------------
// Kernel 2: bf16 mma.sync GEMM, BM=BN=128, BK=64, 3-stage cp.async,
// fused softmax-partial epilogue (R10-proven structure; invA prefetched).
// -----------------------------------------------------------------------------
#define NKT 8            // DIM / 64
#define GEMM_SMEM (98304 + 512)

__global__ __launch_bounds__(256) void gemm_fused_kernel(const float* __restrict__ wp,
                                                         const float* __restrict__ bp) {
    extern __shared__ __align__(1024) char smem[];
    float* se_sm = (float*)(smem + 98304);

    int tid = threadIdx.x;
    int lane = tid & 31, wid = tid >> 5;
    int warp_m = wid & 1, warp_n = wid >> 1;
    int mBase = blockIdx.y * 128, nBase = blockIdx.x * 128;

    uint32_t sbase = smem_u32(smem);

    int arow = tid >> 3, ag = tid & 7;
    int brow = tid >> 4, bg = tid & 15;
    const __nv_bfloat16* aptr = g_A + (size_t)(mBase + arow) * DIM + ag * 8;
    const __nv_bfloat16* bptr = g_B + (size_t)brow * NSPK + nBase + bg * 8;

    // prefetch epilogue scalars (hide latency under the mainloop)
    float wv = *wp, bv = *bp;
    float invs[4][2];
#pragma unroll
    for (int mt = 0; mt < 4; ++mt)
#pragma unroll
        for (int sr = 0; sr < 2; ++sr)
            invs[mt][sr] = g_invA[mBase + warp_m * 64 + mt * 16 + (lane >> 2) + sr * 8];

    float c[4][4][4];
#pragma unroll
    for (int i = 0; i < 4; ++i)
#pragma unroll
        for (int j = 0; j < 4; ++j)
#pragma unroll
            for (int q = 0; q < 4; ++q) c[i][j][q] = 0.f;

#define LOAD_STAGE(s, kt) do {                                                  \
        int k0 = (kt) * 64;                                                     \
        uint32_t sA_ = sbase + (s) * 32768;                                     \
        uint32_t sB_ = sA_ + 16384;                                             \
        CP_ASYNC16(sA_ + aoff2(arow,      ag), aptr + k0);                      \
        CP_ASYNC16(sA_ + aoff2(arow + 32, ag), aptr + k0 + (size_t)32 * DIM);   \
        CP_ASYNC16(sA_ + aoff2(arow + 64, ag), aptr + k0 + (size_t)64 * DIM);   \
        CP_ASYNC16(sA_ + aoff2(arow + 96, ag), aptr + k0 + (size_t)96 * DIM);   \
        CP_ASYNC16(sB_ + boff(brow,      bg), bptr + (size_t)(k0     ) * NSPK); \
        CP_ASYNC16(sB_ + boff(brow + 16, bg), bptr + (size_t)(k0 + 16) * NSPK); \
        CP_ASYNC16(sB_ + boff(brow + 32, bg), bptr + (size_t)(k0 + 32) * NSPK); \
        CP_ASYNC16(sB_ + boff(brow + 48, bg), bptr + (size_t)(k0 + 48) * NSPK); \
        CP_COMMIT();                                                            \
    } while (0)

    LOAD_STAGE(0, 0);
    LOAD_STAGE(1, 1);
    LOAD_STAGE(2, 2);

    int lrow = lane & 15, lsel = lane >> 4;

    for (int kt = 0; kt < NKT; ++kt) {
        if (kt < NKT - 2)       CP_WAIT2();
        else if (kt == NKT - 2) CP_WAIT1();
        else                    CP_WAIT0();
        __syncthreads();

        int s = kt % 3;
        uint32_t sA = sbase + s * 32768;
        uint32_t sB = sA + 16384;

#pragma unroll
        for (int kh = 0; kh < 4; ++kh) {
            uint32_t a[4][4], b[2][4];
#pragma unroll
            for (int mt = 0; mt < 4; ++mt) {
                int row = warp_m * 64 + mt * 16 + lrow;
                LDSM_X4(a[mt], sA + aoff2(row, kh * 2 + lsel));
            }
#pragma unroll
            for (int nt = 0; nt < 2; ++nt) {
                int k = kh * 16 + lrow;
                LDSM_X4T(b[nt], sB + boff(k, warp_n * 4 + nt * 2 + lsel));
            }
#pragma unroll
            for (int mt = 0; mt < 4; ++mt)
#pragma unroll
                for (int n8 = 0; n8 < 4; ++n8) {
                    uint32_t b0 = b[n8 >> 1][(n8 & 1) * 2];
                    uint32_t b1 = b[n8 >> 1][(n8 & 1) * 2 + 1];
                    MMA16816(c[mt][n8], a[mt], b0, b1);
                }
        }
        __syncthreads();
        if (kt + 3 < NKT) LOAD_STAGE((kt + 3) % 3, kt + 3);
    }
#undef LOAD_STAGE

    // ---------------- fused epilogue: partial sum-exp + diag -----------------
    if (tid < 128) se_sm[tid] = 0.f;
    __syncthreads();

#pragma unroll
    for (int mt = 0; mt < 4; ++mt) {
#pragma unroll
        for (int sr = 0; sr < 2; ++sr) {
            int row_l = warp_m * 64 + mt * 16 + (lane >> 2) + sr * 8;
            int row_g = mBase + row_l;
            float sc = wv * invs[mt][sr];
            int jdiag = row_g >> 5;
            float part = 0.f;
#pragma unroll
            for (int n8 = 0; n8 < 4; ++n8) {
#pragma unroll
                for (int cc = 0; cc < 2; ++cc) {
                    int col_g = nBase + warp_n * 32 + n8 * 8 + (lane & 3) * 2 + cc;
                    float v = fmaf(c[mt][n8][sr * 2 + cc], sc, bv);
                    part += __expf(v);
                    if (col_g == jdiag) g_vd[row_g] = v;
                }
            }
            part += __shfl_xor_sync(0xffffffffu, part, 1);
            part += __shfl_xor_sync(0xffffffffu, part, 2);
            if ((lane & 3) == 0) atomicAdd(&se_sm[row_l], part);
        }
    }
    __syncthreads();
    if (tid < 128) atomicAdd(&g_se[mBase + tid], se_sm[tid]);
}

// -----------------------------------------------------------------------------
// Kernel 3: loss = mean(log(se) - vd). Single 1024-thread block, 16 rows/thread.
// -----------------------------------------------------------------------------
__global__ __launch_bounds__(1024) void final_kernel(float* __restrict__ out) {
    int tid = threadIdx.x;
    // batch all loads
    float se[16], vd[16];
#pragma unroll
    for (int i = 0; i < 16; ++i) {
        int idx = i * 1024 + tid;
        se[i] = g_se[idx];
        vd[i] = g_vd[idx];
    }
    float v = 0.f;
#pragma unroll
    for (int i = 0; i < 16; ++i) v += __logf(se[i]) - vd[i];
#pragma unroll
    for (int s = 16; s > 0; s >>= 1) v += __shfl_xor_sync(0xffffffffu, v, s);

    __shared__ float part[32];
    int wid = tid >> 5, lane = tid & 31;
    if (lane == 0) part[wid] = v;
    __syncthreads();
    if (wid == 0) {
        float s = (lane < 32) ? part[lane] : 0.f;
#pragma unroll
        for (int st = 16; st > 0; st >>= 1) s += __shfl_xor_sync(0xffffffffu, s, st);
        if (lane == 0) out[0] = s * (1.0f / (float)MROW);
    }
}

// -----------------------------------------------------------------------------
extern "C" void kernel_launch(void* const* d_in, const int* in_sizes, int n_in,
                              void* d_out, int out_size) {
    const float* e = (const float*)d_in[0];  // (512, 32, 512) fp32
    const float* w = (const float*)d_in[1];
    const float* b = (const float*)d_in[2];
    float* out = (float*)d_out;

    cudaFuncSetAttribute(gemm_fused_kernel,
                         cudaFuncAttributeMaxDynamicSharedMemorySize, GEMM_SMEM);

    conv_kernel<<<MROW / 32, 256>>>(e, out);
    centroid_kernel<<<NSPK, 256>>>(e);
    gemm_fused_kernel<<<dim3(NSPK / 128, MROW / 128), 256, GEMM_SMEM>>>(w, b);
    final_kernel<<<1, 1024>>>(out);
}

// round 15
// speedup vs baseline: 1.0712x; 1.0240x over previous
#include <cuda_runtime.h>
#include <cuda_bf16.h>
#include <math.h>
#include <stdint.h>

#define NSPK 512
#define UUT  32
#define DIM  512
#define MROW 16384          // 512*32
#define EPSF 1e-8f

// ------------------------- device scratch (no allocs) ------------------------
__device__ __nv_bfloat16 g_A[(size_t)MROW * DIM];   // 16 MB bf16(e)
__device__ __nv_bfloat16 g_B[(size_t)DIM * NSPK];   // 512x512 normalized centroids [k][n]
__device__ float g_invA[MROW];
__device__ float g_se[MROW];                        // sum of exp per row
__device__ float g_vd[MROW];                        // diag value per row

// ------------------------------- PTX helpers ---------------------------------
__device__ __forceinline__ uint32_t smem_u32(const void* p) {
    uint32_t a;
    asm("{ .reg .u64 t; cvta.to.shared.u64 t, %1; cvt.u32.u64 %0, t; }"
        : "=r"(a) : "l"(p));
    return a;
}

#define CP_ASYNC16(dst, src) \
    asm volatile("cp.async.cg.shared.global [%0], [%1], 16;" :: "r"(dst), "l"(src))
#define CP_COMMIT() asm volatile("cp.async.commit_group;" ::: "memory")
#define CP_WAIT2()  asm volatile("cp.async.wait_group 2;" ::: "memory")
#define CP_WAIT1()  asm volatile("cp.async.wait_group 1;" ::: "memory")
#define CP_WAIT0()  asm volatile("cp.async.wait_group 0;" ::: "memory")

#define LDSM_X4(r, addr) \
    asm volatile("ldmatrix.sync.aligned.m8n8.x4.shared.b16 {%0,%1,%2,%3}, [%4];" \
        : "=r"((r)[0]), "=r"((r)[1]), "=r"((r)[2]), "=r"((r)[3]) : "r"(addr))
#define LDSM_X4T(r, addr) \
    asm volatile("ldmatrix.sync.aligned.m8n8.x4.trans.shared.b16 {%0,%1,%2,%3}, [%4];" \
        : "=r"((r)[0]), "=r"((r)[1]), "=r"((r)[2]), "=r"((r)[3]) : "r"(addr))

#define MMA16816(c, a, b0, b1) \
    asm volatile("mma.sync.aligned.m16n8k16.row.col.f32.bf16.bf16.f32 " \
        "{%0,%1,%2,%3}, {%4,%5,%6,%7}, {%8,%9}, {%0,%1,%2,%3};" \
        : "+f"((c)[0]), "+f"((c)[1]), "+f"((c)[2]), "+f"((c)[3]) \
        : "r"((a)[0]), "r"((a)[1]), "r"((a)[2]), "r"((a)[3]), "r"(b0), "r"(b1))

// A tile: 128 rows x 128B (64 bf16/row), SW128 swizzle, g = granule 0..7
__device__ __forceinline__ uint32_t aoff2(int row, int g) {
    return (uint32_t)(row * 128 + ((g ^ (row & 7)) << 4));
}
// B tile: 64 rows (k) x 256B (128 bf16), 16 granules/row, XOR with k&7
__device__ __forceinline__ uint32_t boff(int k, int g) {
    return (uint32_t)(k * 256 + ((g ^ (k & 7)) << 4));
}

__device__ __forceinline__ uint32_t pack2(float x, float y) {
    __nv_bfloat162 p;
    p.x = __float2bfloat16(x);
    p.y = __float2bfloat16(y);
    return *reinterpret_cast<uint32_t*>(&p);
}

// -----------------------------------------------------------------------------
// Kernel 1a (conv): streaming convert. warp = 4 rows; ALL 16 LDG.128 batched
// up front (MLP 16/thread). No smem, no barriers. Zeroes g_se and d_out.
// -----------------------------------------------------------------------------
__global__ __launch_bounds__(256) void conv_kernel(const float* __restrict__ e,
                                                   float* __restrict__ out) {
    int w = threadIdx.x >> 5, lane = threadIdx.x & 31;
    int r0 = blockIdx.x * 32 + w * 4;
    if (blockIdx.x == 0 && threadIdx.x == 0) out[0] = 0.f;
    if (lane < 4) g_se[r0 + lane] = 0.f;

    float4 v[4][4];
#pragma unroll
    for (int uu = 0; uu < 4; ++uu) {
        const float4* src = (const float4*)(e + (size_t)(r0 + uu) * DIM);
#pragma unroll
        for (int i = 0; i < 4; ++i) v[uu][i] = src[i * 32 + lane];
    }

    float ss[4];
#pragma unroll
    for (int uu = 0; uu < 4; ++uu) {
        uint2* dst = (uint2*)(g_A + (size_t)(r0 + uu) * DIM);
        float s = 0.f;
#pragma unroll
        for (int i = 0; i < 4; ++i) {
            float4 q = v[uu][i];
            s += q.x * q.x + q.y * q.y + q.z * q.z + q.w * q.w;
            dst[i * 32 + lane] = make_uint2(pack2(q.x, q.y), pack2(q.z, q.w));
        }
        ss[uu] = s;
    }
#pragma unroll
    for (int s = 16; s > 0; s >>= 1) {
#pragma unroll
        for (int uu = 0; uu < 4; ++uu)
            ss[uu] += __shfl_xor_sync(0xffffffffu, ss[uu], s);
    }
    if (lane < 4) g_invA[r0 + lane] = 1.0f / fmaxf(sqrtf(ss[lane]), EPSF);
}

// -----------------------------------------------------------------------------
// Kernel 1b (centroid): block = speaker j; sums over the freshly written bf16
// g_A rows (L2-resident; half the bytes of e) -> g_B [k][n].
// Thread tid owns dims {2tid, 2tid+1}.
// -----------------------------------------------------------------------------
__global__ __launch_bounds__(256) void centroid_kernel() {
    int j = blockIdx.x, tid = threadIdx.x;
    const __nv_bfloat162* base =
        (const __nv_bfloat162*)(g_A + (size_t)j * UUT * DIM) + tid;
    float s0 = 0.f, s1 = 0.f;
#pragma unroll 8
    for (int u = 0; u < UUT; ++u) {
        __nv_bfloat162 p = base[u * (DIM / 2)];
        s0 += __bfloat162float(p.x);
        s1 += __bfloat162float(p.y);
    }
    __shared__ float red[256];
    red[tid] = s0 * s0 + s1 * s1;
    __syncthreads();
    for (int s = 128; s > 0; s >>= 1) {
        if (tid < s) red[tid] += red[tid + s];
        __syncthreads();
    }
    float inv = 1.0f / fmaxf(sqrtf(red[0]), 32.f * EPSF);
    g_B[(size_t)(2 * tid) * NSPK + j]     = __float2bfloat16(s0 * inv);
    g_B[(size_t)(2 * tid + 1) * NSPK + j] = __float2bfloat16(s1 * inv);
}

// -----------------------------------------------------------------------------
// Kernel 2: bf16 mma.sync GEMM, BM=BN=128, BK=64, 3-stage cp.async,
// fused softmax-partial epilogue (R13-proven, unchanged).
// -----------------------------------------------------------------------------
#define NKT 8            // DIM / 64
#define GEMM_SMEM (98304 + 512)

__global__ __launch_bounds__(256) void gemm_fused_kernel(const float* __restrict__ wp,
                                                         const float* __restrict__ bp) {
    extern __shared__ __align__(1024) char smem[];
    float* se_sm = (float*)(smem + 98304);

    int tid = threadIdx.x;
    int lane = tid & 31, wid = tid >> 5;
    int warp_m = wid & 1, warp_n = wid >> 1;
    int mBase = blockIdx.y * 128, nBase = blockIdx.x * 128;

    uint32_t sbase = smem_u32(smem);

    int arow = tid >> 3, ag = tid & 7;
    int brow = tid >> 4, bg = tid & 15;
    const __nv_bfloat16* aptr = g_A + (size_t)(mBase + arow) * DIM + ag * 8;
    const __nv_bfloat16* bptr = g_B + (size_t)brow * NSPK + nBase + bg * 8;

    float wv = *wp, bv = *bp;
    float invs[4][2];
#pragma unroll
    for (int mt = 0; mt < 4; ++mt)
#pragma unroll
        for (int sr = 0; sr < 2; ++sr)
            invs[mt][sr] = g_invA[mBase + warp_m * 64 + mt * 16 + (lane >> 2) + sr * 8];

    float c[4][4][4];
#pragma unroll
    for (int i = 0; i < 4; ++i)
#pragma unroll
        for (int j = 0; j < 4; ++j)
#pragma unroll
            for (int q = 0; q < 4; ++q) c[i][j][q] = 0.f;

#define LOAD_STAGE(s, kt) do {                                                  \
        int k0 = (kt) * 64;                                                     \
        uint32_t sA_ = sbase + (s) * 32768;                                     \
        uint32_t sB_ = sA_ + 16384;                                             \
        CP_ASYNC16(sA_ + aoff2(arow,      ag), aptr + k0);                      \
        CP_ASYNC16(sA_ + aoff2(arow + 32, ag), aptr + k0 + (size_t)32 * DIM);   \
        CP_ASYNC16(sA_ + aoff2(arow + 64, ag), aptr + k0 + (size_t)64 * DIM);   \
        CP_ASYNC16(sA_ + aoff2(arow + 96, ag), aptr + k0 + (size_t)96 * DIM);   \
        CP_ASYNC16(sB_ + boff(brow,      bg), bptr + (size_t)(k0     ) * NSPK); \
        CP_ASYNC16(sB_ + boff(brow + 16, bg), bptr + (size_t)(k0 + 16) * NSPK); \
        CP_ASYNC16(sB_ + boff(brow + 32, bg), bptr + (size_t)(k0 + 32) * NSPK); \
        CP_ASYNC16(sB_ + boff(brow + 48, bg), bptr + (size_t)(k0 + 48) * NSPK); \
        CP_COMMIT();                                                            \
    } while (0)

    LOAD_STAGE(0, 0);
    LOAD_STAGE(1, 1);
    LOAD_STAGE(2, 2);

    int lrow = lane & 15, lsel = lane >> 4;

    for (int kt = 0; kt < NKT; ++kt) {
        if (kt < NKT - 2)       CP_WAIT2();
        else if (kt == NKT - 2) CP_WAIT1();
        else                    CP_WAIT0();
        __syncthreads();

        int s = kt % 3;
        uint32_t sA = sbase + s * 32768;
        uint32_t sB = sA + 16384;

#pragma unroll
        for (int kh = 0; kh < 4; ++kh) {
            uint32_t a[4][4], b[2][4];
#pragma unroll
            for (int mt = 0; mt < 4; ++mt) {
                int row = warp_m * 64 + mt * 16 + lrow;
                LDSM_X4(a[mt], sA + aoff2(row, kh * 2 + lsel));
            }
#pragma unroll
            for (int nt = 0; nt < 2; ++nt) {
                int k = kh * 16 + lrow;
                LDSM_X4T(b[nt], sB + boff(k, warp_n * 4 + nt * 2 + lsel));
            }
#pragma unroll
            for (int mt = 0; mt < 4; ++mt)
#pragma unroll
                for (int n8 = 0; n8 < 4; ++n8) {
                    uint32_t b0 = b[n8 >> 1][(n8 & 1) * 2];
                    uint32_t b1 = b[n8 >> 1][(n8 & 1) * 2 + 1];
                    MMA16816(c[mt][n8], a[mt], b0, b1);
                }
        }
        __syncthreads();
        if (kt + 3 < NKT) LOAD_STAGE((kt + 3) % 3, kt + 3);
    }
#undef LOAD_STAGE

    // ---------------- fused epilogue: partial sum-exp + diag -----------------
    if (tid < 128) se_sm[tid] = 0.f;
    __syncthreads();

#pragma unroll
    for (int mt = 0; mt < 4; ++mt) {
#pragma unroll
        for (int sr = 0; sr < 2; ++sr) {
            int row_l = warp_m * 64 + mt * 16 + (lane >> 2) + sr * 8;
            int row_g = mBase + row_l;
            float sc = wv * invs[mt][sr];
            int jdiag = row_g >> 5;
            float part = 0.f;
#pragma unroll
            for (int n8 = 0; n8 < 4; ++n8) {
#pragma unroll
                for (int cc = 0; cc < 2; ++cc) {
                    int col_g = nBase + warp_n * 32 + n8 * 8 + (lane & 3) * 2 + cc;
                    float v = fmaf(c[mt][n8][sr * 2 + cc], sc, bv);
                    part += __expf(v);
                    if (col_g == jdiag) g_vd[row_g] = v;
                }
            }
            part += __shfl_xor_sync(0xffffffffu, part, 1);
            part += __shfl_xor_sync(0xffffffffu, part, 2);
            if ((lane & 3) == 0) atomicAdd(&se_sm[row_l], part);
        }
    }
    __syncthreads();
    if (tid < 128) atomicAdd(&g_se[mBase + tid], se_sm[tid]);
}

// -----------------------------------------------------------------------------
// Kernel 3: loss = mean(log(se) - vd). 16 blocks x 1024 thr, 1 element/thread.
// -----------------------------------------------------------------------------
__global__ __launch_bounds__(1024) void final_kernel(float* __restrict__ out) {
    int idx = blockIdx.x * 1024 + threadIdx.x;
    float v = __logf(g_se[idx]) - g_vd[idx];
#pragma unroll
    for (int s = 16; s > 0; s >>= 1) v += __shfl_xor_sync(0xffffffffu, v, s);

    __shared__ float part[32];
    int wid = threadIdx.x >> 5, lane = threadIdx.x & 31;
    if (lane == 0) part[wid] = v;
    __syncthreads();
    if (wid == 0) {
        float s = part[lane];
#pragma unroll
        for (int st = 16; st > 0; st >>= 1) s += __shfl_xor_sync(0xffffffffu, s, st);
        if (lane == 0) atomicAdd(out, s * (1.0f / (float)MROW));
    }
}

// -----------------------------------------------------------------------------
extern "C" void kernel_launch(void* const* d_in, const int* in_sizes, int n_in,
                              void* d_out, int out_size) {
    const float* e = (const float*)d_in[0];  // (512, 32, 512) fp32
    const float* w = (const float*)d_in[1];
    const float* b = (const float*)d_in[2];
    float* out = (float*)d_out;

    cudaFuncSetAttribute(gemm_fused_kernel,
                         cudaFuncAttributeMaxDynamicSharedMemorySize, GEMM_SMEM);

    conv_kernel<<<MROW / 32, 256>>>(e, out);
    centroid_kernel<<<NSPK, 256>>>();
    gemm_fused_kernel<<<dim3(NSPK / 128, MROW / 128), 256, GEMM_SMEM>>>(w, b);
    final_kernel<<<MROW / 1024, 1024>>>(out);
}